// round 14
// baseline (speedup 1.0000x reference)
#include <cuda_runtime.h>
#include <cuda_bf16.h>

#define D4 32               // float4 per full row (D=128)
#define QPC 8               // float4-quads per CTA (32 cols = 128B contiguous/row)
#define THREADS 512
#define RB (THREADS / QPC)  // 64 row-bases
#define NWARP (THREADS / 32)

__global__ __launch_bounds__(THREADS, 4)
void graphnorm_rev(const float* __restrict__ x,
                   const float* __restrict__ gamma,
                   const float* __restrict__ beta,
                   const int* __restrict__ batch,
                   float* __restrict__ out)
{
    __shared__ float4 psum[NWARP][QPC];
    __shared__ float4 psq [NWARP][QPC];
    __shared__ float4 smean[QPC], sinv[QPC];

    const int cb   = blockIdx.x;                  // column block 0..3 (fastest)
    const int g    = blockIdx.y;                  // graph
    const int quad = threadIdx.x & (QPC - 1);     // 0..7
    const int rb   = threadIdx.x >> 3;            // 0..63
    const int warp = threadIdx.x >> 5;
    const int lane = threadIdx.x & 31;

    const int start = batch[g];
    const int end   = batch[g + 1];
    const int cnt   = end - start;
    const float fcnt = (float)cnt;

    const float4* __restrict__ xv = (const float4*)x;
    float4* __restrict__ ov = (float4*)out;
    const long colq = (long)cb * QPC + quad;      // float4 col 0..31

    // ---- pass 1: ascending read (lines land in L2), accumulate ----
    float4 s = make_float4(0.f, 0.f, 0.f, 0.f);
    float4 q = make_float4(0.f, 0.f, 0.f, 0.f);
    for (int r = rb; r < cnt; r += RB) {
        float4 v = xv[(long)(start + r) * D4 + colq];
        s.x += v.x; s.y += v.y; s.z += v.z; s.w += v.w;
        q.x += v.x * v.x; q.y += v.y * v.y; q.z += v.z * v.z; q.w += v.w * v.w;
    }

    // ---- warp reduce: lanes {quad, quad+8, quad+16, quad+24} share a column ----
    #pragma unroll
    for (int off = 8; off <= 16; off <<= 1) {
        s.x += __shfl_xor_sync(0xffffffffu, s.x, off);
        s.y += __shfl_xor_sync(0xffffffffu, s.y, off);
        s.z += __shfl_xor_sync(0xffffffffu, s.z, off);
        s.w += __shfl_xor_sync(0xffffffffu, s.w, off);
        q.x += __shfl_xor_sync(0xffffffffu, q.x, off);
        q.y += __shfl_xor_sync(0xffffffffu, q.y, off);
        q.z += __shfl_xor_sync(0xffffffffu, q.z, off);
        q.w += __shfl_xor_sync(0xffffffffu, q.w, off);
    }
    if (lane < QPC) { psum[warp][quad] = s; psq[warp][quad] = q; }
    __syncthreads();

    // ---- final reduce across warps + stats (QPC threads) ----
    if (threadIdx.x < QPC) {
        float4 ts = make_float4(0.f, 0.f, 0.f, 0.f);
        float4 tq = make_float4(0.f, 0.f, 0.f, 0.f);
        #pragma unroll
        for (int w = 0; w < NWARP; w++) {
            float4 a = psum[w][threadIdx.x];
            float4 b = psq [w][threadIdx.x];
            ts.x += a.x; ts.y += a.y; ts.z += a.z; ts.w += a.w;
            tq.x += b.x; tq.y += b.y; tq.z += b.z; tq.w += b.w;
        }
        float4 m, iv;
        m.x = ts.x / fcnt; m.y = ts.y / fcnt; m.z = ts.z / fcnt; m.w = ts.w / fcnt;
        float denom = fcnt - 1.0f;
        iv.x = 1.0f / (sqrtf(fmaxf((tq.x - fcnt * m.x * m.x) / denom, 0.f)) + 1e-5f);
        iv.y = 1.0f / (sqrtf(fmaxf((tq.y - fcnt * m.y * m.y) / denom, 0.f)) + 1e-5f);
        iv.z = 1.0f / (sqrtf(fmaxf((tq.z - fcnt * m.z * m.z) / denom, 0.f)) + 1e-5f);
        iv.w = 1.0f / (sqrtf(fmaxf((tq.w - fcnt * m.w * m.w) / denom, 0.f)) + 1e-5f);
        smean[threadIdx.x] = m;
        sinv [threadIdx.x] = iv;
    }
    __syncthreads();

    // ---- pass 2: DESCENDING re-read (youngest L2 lines first), stream out ----
    const float4 g4 = ((const float4*)gamma)[colq];
    const float4 b4 = ((const float4*)beta)[colq];
    const float4 m  = smean[quad];
    const float4 iv = sinv [quad];

    for (int j = rb; j < cnt; j += RB) {
        const int r = cnt - 1 - j;                // newest lines first
        const long idx = (long)(start + r) * D4 + colq;
        float4 v = __ldcs(&xv[idx]);              // evict-first: dead after read
        float4 o;
        o.x = g4.x * (v.x - m.x) * iv.x + b4.x;
        o.y = g4.y * (v.y - m.y) * iv.y + b4.y;
        o.z = g4.z * (v.z - m.z) * iv.z + b4.z;
        o.w = g4.w * (v.w - m.w) * iv.w + b4.w;
        __stcs(&ov[idx], o);                      // streaming store
    }
}

extern "C" void kernel_launch(void* const* d_in, const int* in_sizes, int n_in,
                              void* d_out, int out_size)
{
    const float* x     = (const float*)d_in[0];
    const float* gamma = (const float*)d_in[1];
    const float* beta  = (const float*)d_in[2];
    const int*   batch = (const int*)d_in[3];
    float* out = (float*)d_out;

    const int G = in_sizes[3] - 1;
    dim3 grid(D4 / QPC, G);   // (column-block fastest, graph)
    graphnorm_rev<<<grid, THREADS>>>(x, gamma, beta, batch, out);
}

// round 15
// speedup vs baseline: 1.2086x; 1.2086x over previous
#include <cuda_runtime.h>
#include <cuda_bf16.h>
#include <cstdint>

#define D4 32               // float4 per full row (D=128)
#define QPC 8               // float4-quads per CTA (32 cols = 128B contiguous/row)
#define NCB 4               // column blocks per row (D4/QPC)
#define THREADS 512
#define RB (THREADS / QPC)  // 64 row-bases
#define NWARP (THREADS / 32)
#define MAXSLOTS 16384      // (graph, column-block) slots

// scratch: per slot, 2 halves x (8 float4 sum + 8 float4 sq) = 32 float4
__device__ float4 g_part[MAXSLOTS * 32];
__device__ int    g_cnt [MAXSLOTS];

__global__ void zero_counters(int nslots) {
    int i = blockIdx.x * blockDim.x + threadIdx.x;
    if (i < nslots) g_cnt[i] = 0;
}

__global__ __launch_bounds__(THREADS, 4)
void graphnorm_split_plain(const float* __restrict__ x,
                           const float* __restrict__ gamma,
                           const float* __restrict__ beta,
                           const int* __restrict__ batch,
                           float* __restrict__ out)
{
    __shared__ float4 psum[NWARP][QPC];
    __shared__ float4 psq [NWARP][QPC];
    __shared__ float4 smean[QPC], sinv[QPC];

    const int hf   = blockIdx.x & 1;              // row half 0/1 (fastest -> pair adjacent)
    const int cb   = blockIdx.x >> 1;             // column block 0..3
    const int g    = blockIdx.y;                  // graph
    const int slot = g * NCB + cb;
    const int quad = threadIdx.x & (QPC - 1);     // 0..7
    const int rb   = threadIdx.x >> 3;            // 0..63
    const int warp = threadIdx.x >> 5;
    const int lane = threadIdx.x & 31;

    const int start = batch[g];
    const int end   = batch[g + 1];
    const int cnt   = end - start;
    const float fcnt = (float)cnt;
    const int hlen    = cnt >> 1;
    const int myStart = start + hf * hlen;
    const int myCnt   = hf ? (cnt - hlen) : hlen;

    const float4* __restrict__ xv = (const float4*)x;
    float4* __restrict__ ov = (float4*)out;
    const long colq = (long)cb * QPC + quad;      // float4 col 0..31

    // ---- pass 1: read my 64KB slice (stays in L2), accumulate sum/sumsq ----
    float4 s = make_float4(0.f, 0.f, 0.f, 0.f);
    float4 q = make_float4(0.f, 0.f, 0.f, 0.f);
    for (int r = rb; r < myCnt; r += RB) {
        float4 v = xv[(long)(myStart + r) * D4 + colq];
        s.x += v.x; s.y += v.y; s.z += v.z; s.w += v.w;
        q.x += v.x * v.x; q.y += v.y * v.y; q.z += v.z * v.z; q.w += v.w * v.w;
    }

    // ---- warp reduce: lanes {quad, quad+8, quad+16, quad+24} share a column ----
    #pragma unroll
    for (int off = 8; off <= 16; off <<= 1) {
        s.x += __shfl_xor_sync(0xffffffffu, s.x, off);
        s.y += __shfl_xor_sync(0xffffffffu, s.y, off);
        s.z += __shfl_xor_sync(0xffffffffu, s.z, off);
        s.w += __shfl_xor_sync(0xffffffffu, s.w, off);
        q.x += __shfl_xor_sync(0xffffffffu, q.x, off);
        q.y += __shfl_xor_sync(0xffffffffu, q.y, off);
        q.z += __shfl_xor_sync(0xffffffffu, q.z, off);
        q.w += __shfl_xor_sync(0xffffffffu, q.w, off);
    }
    if (lane < QPC) { psum[warp][quad] = s; psq[warp][quad] = q; }
    __syncthreads();

    // ---- CTA reduce (threads 0..7) -> publish partial to gmem slot half ----
    if (threadIdx.x < QPC) {
        float4 ts = make_float4(0.f, 0.f, 0.f, 0.f);
        float4 tq = make_float4(0.f, 0.f, 0.f, 0.f);
        #pragma unroll
        for (int w = 0; w < NWARP; w++) {
            float4 a = psum[w][threadIdx.x];
            float4 b = psq [w][threadIdx.x];
            ts.x += a.x; ts.y += a.y; ts.z += a.z; ts.w += a.w;
            tq.x += b.x; tq.y += b.y; tq.z += b.z; tq.w += b.w;
        }
        float4* base = &g_part[(long)slot * 32 + hf * 16];
        base[threadIdx.x]     = ts;
        base[threadIdx.x + 8] = tq;
    }
    __syncthreads();   // all partial stores issued before the release-arrive

    // ---- arrive + spin until both halves published ----
    if (threadIdx.x == 0) {
        asm volatile("red.add.release.gpu.global.s32 [%0], 1;"
                     :: "l"(&g_cnt[slot]) : "memory");
        int v;
        do {
            asm volatile("ld.acquire.gpu.global.s32 %0, [%1];"
                         : "=r"(v) : "l"(&g_cnt[slot]) : "memory");
        } while (v < 2);
    }
    __syncthreads();

    // ---- combine both halves (fixed order: deterministic), compute stats ----
    if (threadIdx.x < QPC) {
        const float4* p0 = &g_part[(long)slot * 32];
        const float4* p1 = &g_part[(long)slot * 32 + 16];
        float4 a0 = p0[threadIdx.x],     a1 = p1[threadIdx.x];
        float4 b0 = p0[threadIdx.x + 8], b1 = p1[threadIdx.x + 8];
        float4 ts, tq;
        ts.x = a0.x + a1.x; ts.y = a0.y + a1.y; ts.z = a0.z + a1.z; ts.w = a0.w + a1.w;
        tq.x = b0.x + b1.x; tq.y = b0.y + b1.y; tq.z = b0.z + b1.z; tq.w = b0.w + b1.w;

        float4 m, iv;
        m.x = ts.x / fcnt; m.y = ts.y / fcnt; m.z = ts.z / fcnt; m.w = ts.w / fcnt;
        float denom = fcnt - 1.0f;
        iv.x = 1.0f / (sqrtf(fmaxf((tq.x - fcnt * m.x * m.x) / denom, 0.f)) + 1e-5f);
        iv.y = 1.0f / (sqrtf(fmaxf((tq.y - fcnt * m.y * m.y) / denom, 0.f)) + 1e-5f);
        iv.z = 1.0f / (sqrtf(fmaxf((tq.z - fcnt * m.z * m.z) / denom, 0.f)) + 1e-5f);
        iv.w = 1.0f / (sqrtf(fmaxf((tq.w - fcnt * m.w * m.w) / denom, 0.f)) + 1e-5f);
        smean[threadIdx.x] = m;
        sinv [threadIdx.x] = iv;
    }
    __syncthreads();

    // ---- pass 2: plain re-read (L2-resident by footprint), plain store ----
    const float4 g4 = ((const float4*)gamma)[colq];
    const float4 b4 = ((const float4*)beta)[colq];
    const float4 m  = smean[quad];
    const float4 iv = sinv [quad];

    for (int r = rb; r < myCnt; r += RB) {
        const long idx = (long)(myStart + r) * D4 + colq;
        float4 v = xv[idx];                   // plain load: L2 hit expected
        float4 o;
        o.x = g4.x * (v.x - m.x) * iv.x + b4.x;
        o.y = g4.y * (v.y - m.y) * iv.y + b4.y;
        o.z = g4.z * (v.z - m.z) * iv.z + b4.z;
        o.w = g4.w * (v.w - m.w) * iv.w + b4.w;
        ov[idx] = o;                          // plain store
    }
}

extern "C" void kernel_launch(void* const* d_in, const int* in_sizes, int n_in,
                              void* d_out, int out_size)
{
    const float* x     = (const float*)d_in[0];
    const float* gamma = (const float*)d_in[1];
    const float* beta  = (const float*)d_in[2];
    const int*   batch = (const int*)d_in[3];
    float* out = (float*)d_out;

    const int G = in_sizes[3] - 1;
    const int nslots = G * NCB;

    zero_counters<<<(nslots + 255) / 256, 256>>>(nslots);

    dim3 grid(2 * NCB, G);   // x = (cb, half) with half fastest -> pairs adjacent
    graphnorm_split_plain<<<grid, THREADS>>>(x, gamma, beta, batch, out);
}

// round 16
// speedup vs baseline: 1.2234x; 1.0122x over previous
#include <cuda_runtime.h>
#include <cuda_bf16.h>
#include <cstdint>

#define D4 32               // float4 per full row (D=128)
#define QPC 8               // float4-quads per CTA (32 cols = 128B contiguous/row)
#define NCB 4               // column blocks per row (D4/QPC)
#define THREADS 512
#define RB (THREADS / QPC)  // 64 row-bases
#define NWARP (THREADS / 32)
#define MAXSLOTS 16384      // (graph, column-block) slots

// scratch: per slot, 2 halves x (8 float4 sum + 8 float4 sq) = 32 float4
__device__ float4 g_part[MAXSLOTS * 32];
__device__ int    g_cnt [MAXSLOTS];

__global__ void zero_counters(int nslots) {
    int i = blockIdx.x * blockDim.x + threadIdx.x;
    if (i < nslots) g_cnt[i] = 0;
}

__global__ __launch_bounds__(THREADS, 4)
void graphnorm_split_sr(const float* __restrict__ x,
                        const float* __restrict__ gamma,
                        const float* __restrict__ beta,
                        const int* __restrict__ batch,
                        float* __restrict__ out)
{
    __shared__ float4 psum[NWARP][QPC];
    __shared__ float4 psq [NWARP][QPC];
    __shared__ float4 smean[QPC], sinv[QPC];

    const int hf   = blockIdx.x & 1;              // row half 0/1 (fastest -> pair adjacent)
    const int cb   = blockIdx.x >> 1;             // column block 0..3
    const int g    = blockIdx.y;                  // graph
    const int slot = g * NCB + cb;
    const int quad = threadIdx.x & (QPC - 1);     // 0..7
    const int rb   = threadIdx.x >> 3;            // 0..63
    const int warp = threadIdx.x >> 5;
    const int lane = threadIdx.x & 31;

    const int start = batch[g];
    const int end   = batch[g + 1];
    const int cnt   = end - start;
    const float fcnt = (float)cnt;
    const int hlen    = cnt >> 1;
    const int myStart = start + hf * hlen;
    const int myCnt   = hf ? (cnt - hlen) : hlen;

    const float4* __restrict__ xv = (const float4*)x;
    float4* __restrict__ ov = (float4*)out;
    const long colq = (long)cb * QPC + quad;      // float4 col 0..31

    // iteration count for this thread's strided rows (no per-iter compare on r)
    const int nit = (myCnt > rb) ? ((myCnt - rb - 1) / RB + 1) : 0;
    const long base = (long)(myStart + rb) * D4 + colq;

    // ---- pass 1: pointer-strided reads, accumulate sum / sumsq ----
    float4 s = make_float4(0.f, 0.f, 0.f, 0.f);
    float4 q = make_float4(0.f, 0.f, 0.f, 0.f);
    {
        const float4* p = xv + base;
        #pragma unroll 4
        for (int i = 0; i < nit; i++) {
            float4 v = *p;
            p += RB * D4;
            s.x += v.x; s.y += v.y; s.z += v.z; s.w += v.w;
            q.x += v.x * v.x; q.y += v.y * v.y; q.z += v.z * v.z; q.w += v.w * v.w;
        }
    }

    // ---- warp reduce: lanes {quad, quad+8, quad+16, quad+24} share a column ----
    #pragma unroll
    for (int off = 8; off <= 16; off <<= 1) {
        s.x += __shfl_xor_sync(0xffffffffu, s.x, off);
        s.y += __shfl_xor_sync(0xffffffffu, s.y, off);
        s.z += __shfl_xor_sync(0xffffffffu, s.z, off);
        s.w += __shfl_xor_sync(0xffffffffu, s.w, off);
        q.x += __shfl_xor_sync(0xffffffffu, q.x, off);
        q.y += __shfl_xor_sync(0xffffffffu, q.y, off);
        q.z += __shfl_xor_sync(0xffffffffu, q.z, off);
        q.w += __shfl_xor_sync(0xffffffffu, q.w, off);
    }
    if (lane < QPC) { psum[warp][quad] = s; psq[warp][quad] = q; }
    __syncthreads();

    // ---- CTA reduce (threads 0..7) -> publish partial to gmem slot half ----
    if (threadIdx.x < QPC) {
        float4 ts = make_float4(0.f, 0.f, 0.f, 0.f);
        float4 tq = make_float4(0.f, 0.f, 0.f, 0.f);
        #pragma unroll
        for (int w = 0; w < NWARP; w++) {
            float4 a = psum[w][threadIdx.x];
            float4 b = psq [w][threadIdx.x];
            ts.x += a.x; ts.y += a.y; ts.z += a.z; ts.w += a.w;
            tq.x += b.x; tq.y += b.y; tq.z += b.z; tq.w += b.w;
        }
        float4* base_p = &g_part[(long)slot * 32 + hf * 16];
        base_p[threadIdx.x]     = ts;
        base_p[threadIdx.x + 8] = tq;
    }
    __syncthreads();   // all partial stores issued before the release-arrive

    // ---- arrive + spin until both halves published ----
    if (threadIdx.x == 0) {
        asm volatile("red.add.release.gpu.global.s32 [%0], 1;"
                     :: "l"(&g_cnt[slot]) : "memory");
        int v;
        do {
            asm volatile("ld.acquire.gpu.global.s32 %0, [%1];"
                         : "=r"(v) : "l"(&g_cnt[slot]) : "memory");
        } while (v < 2);
    }
    __syncthreads();

    // ---- combine both halves (fixed order: deterministic), compute stats ----
    if (threadIdx.x < QPC) {
        const float4* p0 = &g_part[(long)slot * 32];
        const float4* p1 = &g_part[(long)slot * 32 + 16];
        float4 a0 = p0[threadIdx.x],     a1 = p1[threadIdx.x];
        float4 b0 = p0[threadIdx.x + 8], b1 = p1[threadIdx.x + 8];
        float4 ts, tq;
        ts.x = a0.x + a1.x; ts.y = a0.y + a1.y; ts.z = a0.z + a1.z; ts.w = a0.w + a1.w;
        tq.x = b0.x + b1.x; tq.y = b0.y + b1.y; tq.z = b0.z + b1.z; tq.w = b0.w + b1.w;

        float4 m, iv;
        m.x = ts.x / fcnt; m.y = ts.y / fcnt; m.z = ts.z / fcnt; m.w = ts.w / fcnt;
        float denom = fcnt - 1.0f;
        iv.x = 1.0f / (sqrtf(fmaxf((tq.x - fcnt * m.x * m.x) / denom, 0.f)) + 1e-5f);
        iv.y = 1.0f / (sqrtf(fmaxf((tq.y - fcnt * m.y * m.y) / denom, 0.f)) + 1e-5f);
        iv.z = 1.0f / (sqrtf(fmaxf((tq.z - fcnt * m.z * m.z) / denom, 0.f)) + 1e-5f);
        iv.w = 1.0f / (sqrtf(fmaxf((tq.w - fcnt * m.w * m.w) / denom, 0.f)) + 1e-5f);
        smean[threadIdx.x] = m;
        sinv [threadIdx.x] = iv;
    }
    __syncthreads();

    // ---- pass 2: pointer-strided re-read (L2-resident), plain store ----
    const float4 g4 = ((const float4*)gamma)[colq];
    const float4 b4 = ((const float4*)beta)[colq];
    const float4 m  = smean[quad];
    const float4 iv = sinv [quad];

    {
        const float4* p = xv + base;
        float4* po = ov + base;
        #pragma unroll 4
        for (int i = 0; i < nit; i++) {
            float4 v = *p;
            p += RB * D4;
            float4 o;
            o.x = g4.x * (v.x - m.x) * iv.x + b4.x;
            o.y = g4.y * (v.y - m.y) * iv.y + b4.y;
            o.z = g4.z * (v.z - m.z) * iv.z + b4.z;
            o.w = g4.w * (v.w - m.w) * iv.w + b4.w;
            *po = o;
            po += RB * D4;
        }
    }
}

extern "C" void kernel_launch(void* const* d_in, const int* in_sizes, int n_in,
                              void* d_out, int out_size)
{
    const float* x     = (const float*)d_in[0];
    const float* gamma = (const float*)d_in[1];
    const float* beta  = (const float*)d_in[2];
    const int*   batch = (const int*)d_in[3];
    float* out = (float*)d_out;

    const int G = in_sizes[3] - 1;
    const int nslots = G * NCB;

    zero_counters<<<(nslots + 255) / 256, 256>>>(nslots);

    dim3 grid(2 * NCB, G);   // x = (cb, half) with half fastest -> pairs adjacent
    graphnorm_split_sr<<<grid, THREADS>>>(x, gamma, beta, batch, out);
}